// round 14
// baseline (speedup 1.0000x reference)
#include <cuda_runtime.h>
#include <cuda_fp16.h>
#include <stdint.h>

#define M_DIM 2048
#define N_DIM 8192
#define K_DIM 8192

__device__ __align__(128) __half g_A[(size_t)M_DIM * K_DIM];   // 33.5 MB
__device__ __align__(128) __half g_B[(size_t)N_DIM * K_DIM];   // 134 MB

// ---------------------------------------------------------------------------
// Kernel 1 (fused prep): blocks [0,8192) dequant W -> g_B (streaming stores),
// blocks [8192,12288) convert x -> g_A.
// ---------------------------------------------------------------------------
#define DQ_BLOCKS 8192
#define SX_BLOCKS 4096

__global__ void prep_kernel(const float* __restrict__ x,
                            const int* __restrict__ p,
                            const float* __restrict__ cb) {
    if (blockIdx.x < DQ_BLOCKS) {
        int t = blockIdx.x * blockDim.x + threadIdx.x;      // 0 .. 2097151
        const int4* p4 = reinterpret_cast<const int4*>(p) + (size_t)t * 3;
        int4 pa = p4[0], pb = p4[1], pc = p4[2];
        int by[12] = {pa.x, pa.y, pa.z, pa.w, pb.x, pb.y, pb.z, pb.w,
                      pc.x, pc.y, pc.z, pc.w};

        const float4* c4 = reinterpret_cast<const float4*>(cb)
                         + (size_t)(t >> 2) * 2;
        float4 f0 = __ldg(c4), f1 = __ldg(c4 + 1);
        uint64_t t0 = (uint64_t)__half_as_ushort(__float2half_rn(f0.x))
                    | ((uint64_t)__half_as_ushort(__float2half_rn(f0.y)) << 16)
                    | ((uint64_t)__half_as_ushort(__float2half_rn(f0.z)) << 32)
                    | ((uint64_t)__half_as_ushort(__float2half_rn(f0.w)) << 48);
        uint64_t t1 = (uint64_t)__half_as_ushort(__float2half_rn(f1.x))
                    | ((uint64_t)__half_as_ushort(__float2half_rn(f1.y)) << 16)
                    | ((uint64_t)__half_as_ushort(__float2half_rn(f1.z)) << 32)
                    | ((uint64_t)__half_as_ushort(__float2half_rn(f1.w)) << 48);

        uint4* dst = reinterpret_cast<uint4*>(g_B + (size_t)t * 32);
#pragma unroll
        for (int g = 0; g < 4; g++) {
            unsigned bits = (unsigned)by[3 * g] | ((unsigned)by[3 * g + 1] << 8)
                          | ((unsigned)by[3 * g + 2] << 16);
            uint32_t hv[8];
#pragma unroll
            for (int j = 0; j < 8; j++) {
                int idx = (bits >> (3 * j)) & 7;
                uint64_t tab = (idx & 4) ? t1 : t0;
                hv[j] = (uint32_t)(tab >> ((idx & 3) << 4)) & 0xFFFFu;
            }
            uint4 o;
            o.x = hv[0] | (hv[1] << 16);
            o.y = hv[2] | (hv[3] << 16);
            o.z = hv[4] | (hv[5] << 16);
            o.w = hv[6] | (hv[7] << 16);
            __stcs(dst + g, o);
        }
    } else {
        size_t i = ((size_t)(blockIdx.x - DQ_BLOCKS) * blockDim.x
                    + threadIdx.x) * 16;
        float4 v0 = *reinterpret_cast<const float4*>(x + i);
        float4 v1 = *reinterpret_cast<const float4*>(x + i + 4);
        float4 v2 = *reinterpret_cast<const float4*>(x + i + 8);
        float4 v3 = *reinterpret_cast<const float4*>(x + i + 12);
        __half2 h0 = __floats2half2_rn(v0.x, v0.y);
        __half2 h1 = __floats2half2_rn(v0.z, v0.w);
        __half2 h2 = __floats2half2_rn(v1.x, v1.y);
        __half2 h3 = __floats2half2_rn(v1.z, v1.w);
        __half2 h4 = __floats2half2_rn(v2.x, v2.y);
        __half2 h5 = __floats2half2_rn(v2.z, v2.w);
        __half2 h6 = __floats2half2_rn(v3.x, v3.y);
        __half2 h7 = __floats2half2_rn(v3.z, v3.w);
        uint4 o0, o1;
        o0.x = *reinterpret_cast<uint32_t*>(&h0);
        o0.y = *reinterpret_cast<uint32_t*>(&h1);
        o0.z = *reinterpret_cast<uint32_t*>(&h2);
        o0.w = *reinterpret_cast<uint32_t*>(&h3);
        o1.x = *reinterpret_cast<uint32_t*>(&h4);
        o1.y = *reinterpret_cast<uint32_t*>(&h5);
        o1.z = *reinterpret_cast<uint32_t*>(&h6);
        o1.w = *reinterpret_cast<uint32_t*>(&h7);
        *reinterpret_cast<uint4*>(&g_A[i]) = o0;
        *reinterpret_cast<uint4*>(&g_A[i + 8]) = o1;
    }
}

// ---------------------------------------------------------------------------
// Kernel 2: GEMM. BM=BN=128, BK=64, 4 warps, occ2, 3-stage ring,
// K-rotation de-phasing: odd bids start at chunk 64 (mod 128).
// ---------------------------------------------------------------------------
#define BM 128
#define BN 128
#define BK 64
#define NSTAGE 3
#define NITER (K_DIM / BK)               // 128
#define A_BYTES (BM * BK * 2)
#define B_BYTES (BN * BK * 2)
#define STAGE_BYTES (A_BYTES + B_BYTES)
#define GEMM_SMEM (NSTAGE * STAGE_BYTES) // 98304
#define GTHREADS 128

__device__ __forceinline__ uint32_t smem_u32(const void* p) {
    uint32_t a;
    asm("{ .reg .u64 t; cvta.to.shared.u64 t, %1; cvt.u32.u64 %0, t; }"
        : "=r"(a) : "l"(p));
    return a;
}

__device__ __forceinline__ uint32_t swz(uint32_t base, int row, int chunk) {
    return base + row * 128 + (((chunk ^ row) & 7) << 4);
}

__device__ __forceinline__ void cp16(uint32_t dst, const void* src) {
    asm volatile("cp.async.cg.shared.global [%0], [%1], 16;\n"
                 :: "r"(dst), "l"(src));
}

__device__ __forceinline__ void ldsm4(uint32_t* r, uint32_t addr) {
    asm volatile("ldmatrix.sync.aligned.m8n8.x4.shared.b16 {%0,%1,%2,%3}, [%4];"
                 : "=r"(r[0]), "=r"(r[1]), "=r"(r[2]), "=r"(r[3]) : "r"(addr));
}

__device__ __forceinline__ void mma16816(float* c, const uint32_t* a,
                                         const uint32_t* b) {
    asm volatile(
        "mma.sync.aligned.m16n8k16.row.col.f32.f16.f16.f32 "
        "{%0,%1,%2,%3}, {%4,%5,%6,%7}, {%8,%9}, {%0,%1,%2,%3};\n"
        : "+f"(c[0]), "+f"(c[1]), "+f"(c[2]), "+f"(c[3])
        : "r"(a[0]), "r"(a[1]), "r"(a[2]), "r"(a[3]), "r"(b[0]), "r"(b[1]));
}

__global__ void __launch_bounds__(GTHREADS, 2) gemm_kernel(float* __restrict__ y) {
    extern __shared__ char smem[];
    const uint32_t sb = smem_u32(smem);
    const int tid = threadIdx.x;
    const int w = tid >> 5, lane = tid & 31;
    const int wm = (w & 1) * 64;
    const int wn = (w >> 1) * 64;
    const int bm = (blockIdx.x & 15) * BM;
    const int bn = (blockIdx.x >> 4) * BN;
    const int koff = (blockIdx.x & 1) * 64;     // de-phase odd bids by half-K

    float acc[4][8][4];
#pragma unroll
    for (int i = 0; i < 4; i++)
#pragma unroll
        for (int j = 0; j < 8; j++)
#pragma unroll
            for (int r = 0; r < 4; r++) acc[i][j][r] = 0.0f;

    auto load_A = [&](int buf, int chunk) {
        const int k0 = chunk * BK;
        const uint32_t abase = sb + buf * STAGE_BYTES;
#pragma unroll
        for (int i = 0; i < 8; i++) {
            int c = tid + i * GTHREADS;
            int row = c >> 3, ch = c & 7;
            cp16(swz(abase, row, ch),
                 g_A + (size_t)(bm + row) * K_DIM + k0 + ch * 8);
        }
    };
    auto load_B = [&](int buf, int chunk) {
        const int k0 = chunk * BK;
        const uint32_t bbase = sb + buf * STAGE_BYTES + A_BYTES;
#pragma unroll
        for (int i = 0; i < 8; i++) {
            int c = tid + i * GTHREADS;
            int row = c >> 3, ch = c & 7;
            cp16(swz(bbase, row, ch),
                 g_B + (size_t)(bn + row) * K_DIM + k0 + ch * 8);
        }
        asm volatile("cp.async.commit_group;" ::: "memory");
    };

    load_A(0, koff); load_B(0, koff);
    load_A(1, koff + 1); load_B(1, koff + 1);

    uint32_t ra[2][4][4], rb[2][4][4];

    auto ldfrag = [&](uint32_t abase, uint32_t bbase, int kk, int pb) {
#pragma unroll
        for (int mi = 0; mi < 4; mi++) {
            int row = wm + mi * 16 + (lane & 15);
            int ch = kk * 2 + (lane >> 4);
            ldsm4(ra[pb][mi], swz(abase, row, ch));
        }
#pragma unroll
        for (int np = 0; np < 4; np++) {
            int row = wn + np * 16 + (lane & 7) + ((lane >> 4) << 3);
            int ch = kk * 2 + ((lane >> 3) & 1);
            ldsm4(rb[pb][np], swz(bbase, row, ch));
        }
    };

    auto mma_block = [&](int pb) {
#pragma unroll
        for (int mi = 0; mi < 4; mi++)
#pragma unroll
            for (int ni = 0; ni < 8; ni++)
                mma16816(acc[mi][ni], ra[pb][mi], &rb[pb][ni >> 1][(ni & 1) * 2]);
    };

    auto body = [&](int it, int buf) {
        if (it < NITER - 2)
            asm volatile("cp.async.wait_group 1;" ::: "memory");
        else
            asm volatile("cp.async.wait_group 0;" ::: "memory");
        __syncthreads();

        const uint32_t abase = sb + buf * STAGE_BYTES;
        const uint32_t bbase = abase + A_BYTES;
        const int j = it + 2;
        const int jb = (buf + 2) % NSTAGE;
        const int jc = (j + koff) & (NITER - 1);   // rotated chunk index

        ldfrag(abase, bbase, 0, 0);
        if (j < NITER) load_A(jb, jc);
        ldfrag(abase, bbase, 1, 1);
        if (j < NITER) load_B(jb, jc);

        mma_block(0);
        ldfrag(abase, bbase, 2, 0);
        mma_block(1);
        ldfrag(abase, bbase, 3, 1);
        mma_block(0);
        mma_block(1);
    };

    int it = 0;
#pragma unroll 1
    for (int t = 0; t < (NITER - 2) / NSTAGE; t++) {
        body(it, 0);
        body(it + 1, 1);
        body(it + 2, 2);
        it += 3;
    }
    body(126, 0);
    body(127, 1);

    // Epilogue: streaming stores (y is write-once)
#pragma unroll
    for (int mi = 0; mi < 4; mi++) {
#pragma unroll
        for (int ni = 0; ni < 8; ni++) {
            int row = bm + wm + mi * 16 + (lane >> 2);
            int col = bn + wn + ni * 8 + (lane & 3) * 2;
            __stcs(reinterpret_cast<float2*>(&y[(size_t)row * N_DIM + col]),
                   make_float2(acc[mi][ni][0], acc[mi][ni][1]));
            __stcs(reinterpret_cast<float2*>(&y[(size_t)(row + 8) * N_DIM + col]),
                   make_float2(acc[mi][ni][2], acc[mi][ni][3]));
        }
    }
}

// ---------------------------------------------------------------------------
extern "C" void kernel_launch(void* const* d_in, const int* in_sizes, int n_in,
                              void* d_out, int out_size) {
    const float* x  = (const float*)d_in[0];
    const int*   p  = (const int*)d_in[1];
    const float* cb = (const float*)d_in[2];
    float* y = (float*)d_out;

    prep_kernel<<<DQ_BLOCKS + SX_BLOCKS, 256>>>(x, p, cb);

    cudaFuncSetAttribute(gemm_kernel,
                         cudaFuncAttributeMaxDynamicSharedMemorySize, GEMM_SMEM);
    gemm_kernel<<<1024, GTHREADS, GEMM_SMEM>>>(y);
}

// round 15
// speedup vs baseline: 1.0483x; 1.0483x over previous
#include <cuda_runtime.h>
#include <cuda_fp16.h>
#include <stdint.h>

#define M_DIM 2048
#define N_DIM 8192
#define K_DIM 8192

__device__ __align__(128) __half g_A[(size_t)M_DIM * K_DIM];   // 33.5 MB
__device__ __align__(128) __half g_B[(size_t)N_DIM * K_DIM];   // 134 MB

// ---------------------------------------------------------------------------
// Kernel 1: x (fp32) -> fp16   (4 float4 per thread)
// ---------------------------------------------------------------------------
__global__ void split_x_kernel(const float* __restrict__ x) {
    size_t i = ((size_t)blockIdx.x * blockDim.x + threadIdx.x) * 16;
    float4 v0 = *reinterpret_cast<const float4*>(x + i);
    float4 v1 = *reinterpret_cast<const float4*>(x + i + 4);
    float4 v2 = *reinterpret_cast<const float4*>(x + i + 8);
    float4 v3 = *reinterpret_cast<const float4*>(x + i + 12);
    __half2 h0 = __floats2half2_rn(v0.x, v0.y);
    __half2 h1 = __floats2half2_rn(v0.z, v0.w);
    __half2 h2 = __floats2half2_rn(v1.x, v1.y);
    __half2 h3 = __floats2half2_rn(v1.z, v1.w);
    __half2 h4 = __floats2half2_rn(v2.x, v2.y);
    __half2 h5 = __floats2half2_rn(v2.z, v2.w);
    __half2 h6 = __floats2half2_rn(v3.x, v3.y);
    __half2 h7 = __floats2half2_rn(v3.z, v3.w);
    uint4 o0, o1;
    o0.x = *reinterpret_cast<uint32_t*>(&h0);
    o0.y = *reinterpret_cast<uint32_t*>(&h1);
    o0.z = *reinterpret_cast<uint32_t*>(&h2);
    o0.w = *reinterpret_cast<uint32_t*>(&h3);
    o1.x = *reinterpret_cast<uint32_t*>(&h4);
    o1.y = *reinterpret_cast<uint32_t*>(&h5);
    o1.z = *reinterpret_cast<uint32_t*>(&h6);
    o1.w = *reinterpret_cast<uint32_t*>(&h7);
    *reinterpret_cast<uint4*>(&g_A[i]) = o0;
    *reinterpret_cast<uint4*>(&g_A[i + 8]) = o1;
}

// ---------------------------------------------------------------------------
// Kernel 2: dequant. 4 groups (32 weights) per thread; streaming stores.
// ---------------------------------------------------------------------------
__global__ void dequant_kernel(const int* __restrict__ p,
                               const float* __restrict__ cb) {
    int t = blockIdx.x * blockDim.x + threadIdx.x;      // 0 .. 2097151
    const int4* p4 = reinterpret_cast<const int4*>(p) + (size_t)t * 3;
    int4 pa = p4[0], pb = p4[1], pc = p4[2];
    int by[12] = {pa.x, pa.y, pa.z, pa.w, pb.x, pb.y, pb.z, pb.w,
                  pc.x, pc.y, pc.z, pc.w};

    const float4* c4 = reinterpret_cast<const float4*>(cb) + (size_t)(t >> 2) * 2;
    float4 f0 = __ldg(c4), f1 = __ldg(c4 + 1);
    uint64_t t0 = (uint64_t)__half_as_ushort(__float2half_rn(f0.x))
                | ((uint64_t)__half_as_ushort(__float2half_rn(f0.y)) << 16)
                | ((uint64_t)__half_as_ushort(__float2half_rn(f0.z)) << 32)
                | ((uint64_t)__half_as_ushort(__float2half_rn(f0.w)) << 48);
    uint64_t t1 = (uint64_t)__half_as_ushort(__float2half_rn(f1.x))
                | ((uint64_t)__half_as_ushort(__float2half_rn(f1.y)) << 16)
                | ((uint64_t)__half_as_ushort(__float2half_rn(f1.z)) << 32)
                | ((uint64_t)__half_as_ushort(__float2half_rn(f1.w)) << 48);

    uint4* dst = reinterpret_cast<uint4*>(g_B + (size_t)t * 32);
#pragma unroll
    for (int g = 0; g < 4; g++) {
        unsigned bits = (unsigned)by[3 * g] | ((unsigned)by[3 * g + 1] << 8)
                      | ((unsigned)by[3 * g + 2] << 16);
        uint32_t hv[8];
#pragma unroll
        for (int j = 0; j < 8; j++) {
            int idx = (bits >> (3 * j)) & 7;
            uint64_t tab = (idx & 4) ? t1 : t0;
            hv[j] = (uint32_t)(tab >> ((idx & 3) << 4)) & 0xFFFFu;
        }
        uint4 o;
        o.x = hv[0] | (hv[1] << 16);
        o.y = hv[2] | (hv[3] << 16);
        o.z = hv[4] | (hv[5] << 16);
        o.w = hv[6] | (hv[7] << 16);
        __stcs(dst + g, o);               // write-once: evict-first in L2
    }
}

// ---------------------------------------------------------------------------
// Kernel 3: GEMM (R10-exact). BM=BN=128, BK=64, 4 warps, occ2, 3-stage ring,
// x3-unrolled loop (compile-time stage index), split A/B cp.async issue.
// ---------------------------------------------------------------------------
#define BM 128
#define BN 128
#define BK 64
#define NSTAGE 3
#define NITER (K_DIM / BK)               // 128
#define A_BYTES (BM * BK * 2)
#define B_BYTES (BN * BK * 2)
#define STAGE_BYTES (A_BYTES + B_BYTES)
#define GEMM_SMEM (NSTAGE * STAGE_BYTES) // 98304
#define GTHREADS 128

__device__ __forceinline__ uint32_t smem_u32(const void* p) {
    uint32_t a;
    asm("{ .reg .u64 t; cvta.to.shared.u64 t, %1; cvt.u32.u64 %0, t; }"
        : "=r"(a) : "l"(p));
    return a;
}

__device__ __forceinline__ uint32_t swz(uint32_t base, int row, int chunk) {
    return base + row * 128 + (((chunk ^ row) & 7) << 4);
}

__device__ __forceinline__ void cp16(uint32_t dst, const void* src) {
    asm volatile("cp.async.cg.shared.global [%0], [%1], 16;\n"
                 :: "r"(dst), "l"(src));
}

__device__ __forceinline__ void ldsm4(uint32_t* r, uint32_t addr) {
    asm volatile("ldmatrix.sync.aligned.m8n8.x4.shared.b16 {%0,%1,%2,%3}, [%4];"
                 : "=r"(r[0]), "=r"(r[1]), "=r"(r[2]), "=r"(r[3]) : "r"(addr));
}

__device__ __forceinline__ void mma16816(float* c, const uint32_t* a,
                                         const uint32_t* b) {
    asm volatile(
        "mma.sync.aligned.m16n8k16.row.col.f32.f16.f16.f32 "
        "{%0,%1,%2,%3}, {%4,%5,%6,%7}, {%8,%9}, {%0,%1,%2,%3};\n"
        : "+f"(c[0]), "+f"(c[1]), "+f"(c[2]), "+f"(c[3])
        : "r"(a[0]), "r"(a[1]), "r"(a[2]), "r"(a[3]), "r"(b[0]), "r"(b[1]));
}

__global__ void __launch_bounds__(GTHREADS, 2) gemm_kernel(float* __restrict__ y) {
    extern __shared__ char smem[];
    const uint32_t sb = smem_u32(smem);
    const int tid = threadIdx.x;
    const int w = tid >> 5, lane = tid & 31;
    const int wm = (w & 1) * 64;
    const int wn = (w >> 1) * 64;
    const int bm = (blockIdx.x & 15) * BM;     // M fastest -> B stripe shared
    const int bn = (blockIdx.x >> 4) * BN;

    float acc[4][8][4];
#pragma unroll
    for (int i = 0; i < 4; i++)
#pragma unroll
        for (int j = 0; j < 8; j++)
#pragma unroll
            for (int r = 0; r < 4; r++) acc[i][j][r] = 0.0f;

    auto load_A = [&](int buf, int chunk) {
        const int k0 = chunk * BK;
        const uint32_t abase = sb + buf * STAGE_BYTES;
#pragma unroll
        for (int i = 0; i < 8; i++) {
            int c = tid + i * GTHREADS;
            int row = c >> 3, ch = c & 7;
            cp16(swz(abase, row, ch),
                 g_A + (size_t)(bm + row) * K_DIM + k0 + ch * 8);
        }
    };
    auto load_B = [&](int buf, int chunk) {
        const int k0 = chunk * BK;
        const uint32_t bbase = sb + buf * STAGE_BYTES + A_BYTES;
#pragma unroll
        for (int i = 0; i < 8; i++) {
            int c = tid + i * GTHREADS;
            int row = c >> 3, ch = c & 7;
            cp16(swz(bbase, row, ch),
                 g_B + (size_t)(bn + row) * K_DIM + k0 + ch * 8);
        }
        asm volatile("cp.async.commit_group;" ::: "memory");
    };

    load_A(0, 0); load_B(0, 0);
    load_A(1, 1); load_B(1, 1);

    uint32_t ra[2][4][4], rb[2][4][4];

    auto ldfrag = [&](uint32_t abase, uint32_t bbase, int kk, int pb) {
#pragma unroll
        for (int mi = 0; mi < 4; mi++) {
            int row = wm + mi * 16 + (lane & 15);
            int ch = kk * 2 + (lane >> 4);
            ldsm4(ra[pb][mi], swz(abase, row, ch));
        }
#pragma unroll
        for (int np = 0; np < 4; np++) {
            int row = wn + np * 16 + (lane & 7) + ((lane >> 4) << 3);
            int ch = kk * 2 + ((lane >> 3) & 1);
            ldsm4(rb[pb][np], swz(bbase, row, ch));
        }
    };

    auto mma_block = [&](int pb) {
#pragma unroll
        for (int mi = 0; mi < 4; mi++)
#pragma unroll
            for (int ni = 0; ni < 8; ni++)
                mma16816(acc[mi][ni], ra[pb][mi], &rb[pb][ni >> 1][(ni & 1) * 2]);
    };

    auto body = [&](int it, int buf) {
        if (it < NITER - 2)
            asm volatile("cp.async.wait_group 1;" ::: "memory");
        else
            asm volatile("cp.async.wait_group 0;" ::: "memory");
        __syncthreads();

        const uint32_t abase = sb + buf * STAGE_BYTES;
        const uint32_t bbase = abase + A_BYTES;
        const int j = it + 2;
        const int jb = (buf + 2) % NSTAGE;

        ldfrag(abase, bbase, 0, 0);
        if (j < NITER) load_A(jb, j);
        ldfrag(abase, bbase, 1, 1);
        if (j < NITER) load_B(jb, j);

        mma_block(0);
        ldfrag(abase, bbase, 2, 0);
        mma_block(1);
        ldfrag(abase, bbase, 3, 1);
        mma_block(0);
        mma_block(1);
    };

    int it = 0;
#pragma unroll 1
    for (int t = 0; t < (NITER - 2) / NSTAGE; t++) {
        body(it, 0);
        body(it + 1, 1);
        body(it + 2, 2);
        it += 3;
    }
    body(126, 0);
    body(127, 1);

#pragma unroll
    for (int mi = 0; mi < 4; mi++) {
#pragma unroll
        for (int ni = 0; ni < 8; ni++) {
            int row = bm + wm + mi * 16 + (lane >> 2);
            int col = bn + wn + ni * 8 + (lane & 3) * 2;
            *reinterpret_cast<float2*>(&y[(size_t)row * N_DIM + col]) =
                make_float2(acc[mi][ni][0], acc[mi][ni][1]);
            *reinterpret_cast<float2*>(&y[(size_t)(row + 8) * N_DIM + col]) =
                make_float2(acc[mi][ni][2], acc[mi][ni][3]);
        }
    }
}

// ---------------------------------------------------------------------------
extern "C" void kernel_launch(void* const* d_in, const int* in_sizes, int n_in,
                              void* d_out, int out_size) {
    const float* x  = (const float*)d_in[0];
    const int*   p  = (const int*)d_in[1];
    const float* cb = (const float*)d_in[2];
    float* y = (float*)d_out;

    split_x_kernel<<<(M_DIM * (size_t)K_DIM / 16) / 256, 256>>>(x);
    dequant_kernel<<<8192, 256>>>(p, cb);

    cudaFuncSetAttribute(gemm_kernel,
                         cudaFuncAttributeMaxDynamicSharedMemorySize, GEMM_SMEM);
    gemm_kernel<<<1024, GTHREADS, GEMM_SMEM>>>(y);
}

// round 16
// speedup vs baseline: 1.0967x; 1.0462x over previous
#include <cuda_runtime.h>
#include <cuda_fp16.h>
#include <stdint.h>

#define M_DIM 2048
#define N_DIM 8192
#define K_DIM 8192

__device__ __align__(128) __half g_A[(size_t)M_DIM * K_DIM];   // 33.5 MB
__device__ __align__(128) __half g_B[(size_t)N_DIM * K_DIM];   // 134 MB

// ---------------------------------------------------------------------------
// Kernel 1: x (fp32) -> fp16   (4 float4 per thread)
// ---------------------------------------------------------------------------
__global__ void split_x_kernel(const float* __restrict__ x) {
    size_t i = ((size_t)blockIdx.x * blockDim.x + threadIdx.x) * 16;
    float4 v0 = *reinterpret_cast<const float4*>(x + i);
    float4 v1 = *reinterpret_cast<const float4*>(x + i + 4);
    float4 v2 = *reinterpret_cast<const float4*>(x + i + 8);
    float4 v3 = *reinterpret_cast<const float4*>(x + i + 12);
    __half2 h0 = __floats2half2_rn(v0.x, v0.y);
    __half2 h1 = __floats2half2_rn(v0.z, v0.w);
    __half2 h2 = __floats2half2_rn(v1.x, v1.y);
    __half2 h3 = __floats2half2_rn(v1.z, v1.w);
    __half2 h4 = __floats2half2_rn(v2.x, v2.y);
    __half2 h5 = __floats2half2_rn(v2.z, v2.w);
    __half2 h6 = __floats2half2_rn(v3.x, v3.y);
    __half2 h7 = __floats2half2_rn(v3.z, v3.w);
    uint4 o0, o1;
    o0.x = *reinterpret_cast<uint32_t*>(&h0);
    o0.y = *reinterpret_cast<uint32_t*>(&h1);
    o0.z = *reinterpret_cast<uint32_t*>(&h2);
    o0.w = *reinterpret_cast<uint32_t*>(&h3);
    o1.x = *reinterpret_cast<uint32_t*>(&h4);
    o1.y = *reinterpret_cast<uint32_t*>(&h5);
    o1.z = *reinterpret_cast<uint32_t*>(&h6);
    o1.w = *reinterpret_cast<uint32_t*>(&h7);
    *reinterpret_cast<uint4*>(&g_A[i]) = o0;
    *reinterpret_cast<uint4*>(&g_A[i + 8]) = o1;
}

// ---------------------------------------------------------------------------
// Kernel 2: dequant. 4 groups (32 weights) per thread; streaming stores.
// ---------------------------------------------------------------------------
__global__ void dequant_kernel(const int* __restrict__ p,
                               const float* __restrict__ cb) {
    int t = blockIdx.x * blockDim.x + threadIdx.x;      // 0 .. 2097151
    const int4* p4 = reinterpret_cast<const int4*>(p) + (size_t)t * 3;
    int4 pa = p4[0], pb = p4[1], pc = p4[2];
    int by[12] = {pa.x, pa.y, pa.z, pa.w, pb.x, pb.y, pb.z, pb.w,
                  pc.x, pc.y, pc.z, pc.w};

    const float4* c4 = reinterpret_cast<const float4*>(cb) + (size_t)(t >> 2) * 2;
    float4 f0 = __ldg(c4), f1 = __ldg(c4 + 1);
    uint64_t t0 = (uint64_t)__half_as_ushort(__float2half_rn(f0.x))
                | ((uint64_t)__half_as_ushort(__float2half_rn(f0.y)) << 16)
                | ((uint64_t)__half_as_ushort(__float2half_rn(f0.z)) << 32)
                | ((uint64_t)__half_as_ushort(__float2half_rn(f0.w)) << 48);
    uint64_t t1 = (uint64_t)__half_as_ushort(__float2half_rn(f1.x))
                | ((uint64_t)__half_as_ushort(__float2half_rn(f1.y)) << 16)
                | ((uint64_t)__half_as_ushort(__float2half_rn(f1.z)) << 32)
                | ((uint64_t)__half_as_ushort(__float2half_rn(f1.w)) << 48);

    uint4* dst = reinterpret_cast<uint4*>(g_B + (size_t)t * 32);
#pragma unroll
    for (int g = 0; g < 4; g++) {
        unsigned bits = (unsigned)by[3 * g] | ((unsigned)by[3 * g + 1] << 8)
                      | ((unsigned)by[3 * g + 2] << 16);
        uint32_t hv[8];
#pragma unroll
        for (int j = 0; j < 8; j++) {
            int idx = (bits >> (3 * j)) & 7;
            uint64_t tab = (idx & 4) ? t1 : t0;
            hv[j] = (uint32_t)(tab >> ((idx & 3) << 4)) & 0xFFFFu;
        }
        uint4 o;
        o.x = hv[0] | (hv[1] << 16);
        o.y = hv[2] | (hv[3] << 16);
        o.z = hv[4] | (hv[5] << 16);
        o.w = hv[6] | (hv[7] << 16);
        __stcs(dst + g, o);
    }
}

// ---------------------------------------------------------------------------
// Kernel 3: GEMM. BM=BN=128, BK=64, 4 warps, occ2, 3-stage ring.
// Late-barrier pipeline: wait+sync after kk2; next iter's kk0 fragments
// prefetched right after the barrier, hidden under kk3's mma block.
// ---------------------------------------------------------------------------
#define BM 128
#define BN 128
#define BK 64
#define NSTAGE 3
#define NITER (K_DIM / BK)               // 128
#define A_BYTES (BM * BK * 2)
#define B_BYTES (BN * BK * 2)
#define STAGE_BYTES (A_BYTES + B_BYTES)
#define GEMM_SMEM (NSTAGE * STAGE_BYTES) // 98304
#define GTHREADS 128

__device__ __forceinline__ uint32_t smem_u32(const void* p) {
    uint32_t a;
    asm("{ .reg .u64 t; cvta.to.shared.u64 t, %1; cvt.u32.u64 %0, t; }"
        : "=r"(a) : "l"(p));
    return a;
}

__device__ __forceinline__ uint32_t swz(uint32_t base, int row, int chunk) {
    return base + row * 128 + (((chunk ^ row) & 7) << 4);
}

__device__ __forceinline__ void cp16(uint32_t dst, const void* src) {
    asm volatile("cp.async.cg.shared.global [%0], [%1], 16;\n"
                 :: "r"(dst), "l"(src));
}

__device__ __forceinline__ void ldsm4(uint32_t* r, uint32_t addr) {
    asm volatile("ldmatrix.sync.aligned.m8n8.x4.shared.b16 {%0,%1,%2,%3}, [%4];"
                 : "=r"(r[0]), "=r"(r[1]), "=r"(r[2]), "=r"(r[3]) : "r"(addr));
}

__device__ __forceinline__ void mma16816(float* c, const uint32_t* a,
                                         const uint32_t* b) {
    asm volatile(
        "mma.sync.aligned.m16n8k16.row.col.f32.f16.f16.f32 "
        "{%0,%1,%2,%3}, {%4,%5,%6,%7}, {%8,%9}, {%0,%1,%2,%3};\n"
        : "+f"(c[0]), "+f"(c[1]), "+f"(c[2]), "+f"(c[3])
        : "r"(a[0]), "r"(a[1]), "r"(a[2]), "r"(a[3]), "r"(b[0]), "r"(b[1]));
}

__global__ void __launch_bounds__(GTHREADS, 2) gemm_kernel(float* __restrict__ y) {
    extern __shared__ char smem[];
    const uint32_t sb = smem_u32(smem);
    const int tid = threadIdx.x;
    const int w = tid >> 5, lane = tid & 31;
    const int wm = (w & 1) * 64;
    const int wn = (w >> 1) * 64;
    const int bm = (blockIdx.x & 15) * BM;     // M fastest -> B stripe shared
    const int bn = (blockIdx.x >> 4) * BN;

    float acc[4][8][4];
#pragma unroll
    for (int i = 0; i < 4; i++)
#pragma unroll
        for (int j = 0; j < 8; j++)
#pragma unroll
            for (int r = 0; r < 4; r++) acc[i][j][r] = 0.0f;

    auto load_A = [&](int buf, int chunk) {
        const int k0 = chunk * BK;
        const uint32_t abase = sb + buf * STAGE_BYTES;
#pragma unroll
        for (int i = 0; i < 8; i++) {
            int c = tid + i * GTHREADS;
            int row = c >> 3, ch = c & 7;
            cp16(swz(abase, row, ch),
                 g_A + (size_t)(bm + row) * K_DIM + k0 + ch * 8);
        }
    };
    auto load_B = [&](int buf, int chunk) {
        const int k0 = chunk * BK;
        const uint32_t bbase = sb + buf * STAGE_BYTES + A_BYTES;
#pragma unroll
        for (int i = 0; i < 8; i++) {
            int c = tid + i * GTHREADS;
            int row = c >> 3, ch = c & 7;
            cp16(swz(bbase, row, ch),
                 g_B + (size_t)(bn + row) * K_DIM + k0 + ch * 8);
        }
        asm volatile("cp.async.commit_group;" ::: "memory");
    };

    uint32_t ra[2][4][4], rb[2][4][4];

    auto ldfrag = [&](uint32_t abase, uint32_t bbase, int kk, int pb) {
#pragma unroll
        for (int mi = 0; mi < 4; mi++) {
            int row = wm + mi * 16 + (lane & 15);
            int ch = kk * 2 + (lane >> 4);
            ldsm4(ra[pb][mi], swz(abase, row, ch));
        }
#pragma unroll
        for (int np = 0; np < 4; np++) {
            int row = wn + np * 16 + (lane & 7) + ((lane >> 4) << 3);
            int ch = kk * 2 + ((lane >> 3) & 1);
            ldsm4(rb[pb][np], swz(bbase, row, ch));
        }
    };

    auto mma_block = [&](int pb) {
#pragma unroll
        for (int mi = 0; mi < 4; mi++)
#pragma unroll
            for (int ni = 0; ni < 8; ni++)
                mma16816(acc[mi][ni], ra[pb][mi], &rb[pb][ni >> 1][(ni & 1) * 2]);
    };

    // Prologue: fill stages 0,1; make stage 0 visible; prefetch kk0 of iter 0.
    load_A(0, 0); load_B(0, 0);
    load_A(1, 1); load_B(1, 1);
    asm volatile("cp.async.wait_group 1;" ::: "memory");   // stage 0 done
    __syncthreads();                                        // cross-thread visible
    ldfrag(sb, sb + A_BYTES, 0, 0);                         // kk0 of iter 0

    // Body invariant at entry: kk0 frags of iter 'it' already in pb=0 regs;
    // stage 'it' complete and visible to all threads.
    auto body = [&](int it, int buf) {
        const uint32_t abase = sb + buf * STAGE_BYTES;
        const uint32_t bbase = abase + A_BYTES;
        const int j = it + 2;
        const int jb = (buf + 2) % NSTAGE;

        ldfrag(abase, bbase, 1, 1);            // kk1 frags
        if (j < NITER) { load_A(jb, j); load_B(jb, j); }   // issue + commit

        mma_block(0);                          // kk0 (prefetched)
        ldfrag(abase, bbase, 2, 0);
        mma_block(1);                          // kk1
        ldfrag(abase, bbase, 3, 1);
        mma_block(0);                          // kk2

        if (it < NITER - 2)
            asm volatile("cp.async.wait_group 1;" ::: "memory"); // stage it+1 done
        else
            asm volatile("cp.async.wait_group 0;" ::: "memory");
        __syncthreads();                       // visibility + slot-reuse guard

        if (it + 1 < NITER) {                  // prefetch kk0 of iter it+1
            const uint32_t nab = sb + ((buf + 1) % NSTAGE) * STAGE_BYTES;
            ldfrag(nab, nab + A_BYTES, 0, 0);
        }
        mma_block(1);                          // kk3 hides the prefetch ramp
    };

    int it = 0;
#pragma unroll 1
    for (int t = 0; t < (NITER - 2) / NSTAGE; t++) {   // iters 0..125
        body(it, 0);
        body(it + 1, 1);
        body(it + 2, 2);
        it += 3;
    }
    body(126, 0);
    body(127, 1);

    // Epilogue
#pragma unroll
    for (int mi = 0; mi < 4; mi++) {
#pragma unroll
        for (int ni = 0; ni < 8; ni++) {
            int row = bm + wm + mi * 16 + (lane >> 2);
            int col = bn + wn + ni * 8 + (lane & 3) * 2;
            *reinterpret_cast<float2*>(&y[(size_t)row * N_DIM + col]) =
                make_float2(acc[mi][ni][0], acc[mi][ni][1]);
            *reinterpret_cast<float2*>(&y[(size_t)(row + 8) * N_DIM + col]) =
                make_float2(acc[mi][ni][2], acc[mi][ni][3]);
        }
    }
}

// ---------------------------------------------------------------------------
extern "C" void kernel_launch(void* const* d_in, const int* in_sizes, int n_in,
                              void* d_out, int out_size) {
    const float* x  = (const float*)d_in[0];
    const int*   p  = (const int*)d_in[1];
    const float* cb = (const float*)d_in[2];
    float* y = (float*)d_out;

    split_x_kernel<<<(M_DIM * (size_t)K_DIM / 16) / 256, 256>>>(x);
    dequant_kernel<<<8192, 256>>>(p, cb);

    cudaFuncSetAttribute(gemm_kernel,
                         cudaFuncAttributeMaxDynamicSharedMemorySize, GEMM_SMEM);
    gemm_kernel<<<1024, GTHREADS, GEMM_SMEM>>>(y);
}